// round 16
// baseline (speedup 1.0000x reference)
#include <cuda_runtime.h>
#include <cuda_bf16.h>
#include <math.h>
#include <stdint.h>

#define B   128
#define T   1024
#define TCC 1024
#define H   512
#define E   256
#define VT  50000
#define OOV 50
#define VO  (VT + OOV)

#define OUT_H_OFF ((size_t)B * VO)
#define OUT_C_OFF (OUT_H_OFF + (size_t)B * H)

// ---------------- scratch ----------------
__device__ float g_x[B * E];
__device__ float g_gates[B * 4 * H];
__device__ float g_hnew[B * H];
__device__ __align__(16) __nv_bfloat16 g_dec_bf16[B * H];
__device__ float g_ctx[B * H];
__device__ float g_cctx[B * H];
__device__ float g_scores[B * TCC];
__device__ float g_m2[B], g_l2[B];
__device__ float g_rsum[B];

__device__ __forceinline__ float sigmoidf_(float x) { return 1.f / (1.f + expf(-x)); }

// ---------------- k0: embed (+ zero gates & rsum) ----------------
__global__ void k_embed(const int* __restrict__ ids, const float* __restrict__ emb) {
    int b = blockIdx.x, e = threadIdx.x;
    float s = 0.f;
#pragma unroll
    for (int l = 0; l < 4; l++) {
        int id = ids[b * 4 + l];
        s += emb[(size_t)id * E + e];
    }
    g_x[b * E + e] = tanhf(s * 0.25f);
    int idx = b * 256 + e;
    for (int i = idx; i < B * 4 * H; i += B * 256) g_gates[i] = 0.f;
    if (idx < B) g_rsum[idx] = 0.f;
}

// ---------------- k1: LSTM gates GEMM, split-K x16 ----------------
__global__ void k_lstm_gemm(const float* __restrict__ h0,
                            const float* __restrict__ W_ih,
                            const float* __restrict__ W_hh) {
    __shared__ float As[128][17];
    __shared__ float Ws[64][17];
    int tid = threadIdx.x;
    int tx = tid & 15, ty = tid >> 4;
    int nb = blockIdx.x;
    int ksp = blockIdx.y;        // K range [ksp*48, +48)
    float acc[8][4];
#pragma unroll
    for (int i = 0; i < 8; i++)
#pragma unroll
        for (int q = 0; q < 4; q++) acc[i][q] = 0.f;

#pragma unroll
    for (int kk = 0; kk < 48; kk += 16) {
        int kg0 = ksp * 48 + kk;
        for (int i = tid; i < 128 * 16; i += 256) {
            int m = i >> 4, kc = i & 15, kg = kg0 + kc;
            As[m][kc] = (kg < 256) ? g_x[m * E + kg] : h0[m * H + (kg - 256)];
        }
        for (int i = tid; i < 64 * 16; i += 256) {
            int n = i >> 4, kc = i & 15, kg = kg0 + kc;
            int ng = nb * 64 + n;
            Ws[n][kc] = (kg < 256) ? W_ih[(size_t)ng * 256 + kg]
                                   : W_hh[(size_t)ng * 512 + (kg - 256)];
        }
        __syncthreads();
#pragma unroll
        for (int k = 0; k < 16; k++) {
            float a[8], wv[4];
#pragma unroll
            for (int i = 0; i < 8; i++) a[i] = As[ty + 16 * i][k];
#pragma unroll
            for (int q = 0; q < 4; q++) wv[q] = Ws[tx * 4 + q][k];
#pragma unroll
            for (int i = 0; i < 8; i++)
#pragma unroll
                for (int q = 0; q < 4; q++) acc[i][q] += a[i] * wv[q];
        }
        __syncthreads();
    }
#pragma unroll
    for (int i = 0; i < 8; i++)
#pragma unroll
        for (int q = 0; q < 4; q++)
            atomicAdd(&g_gates[(ty + 16 * i) * (4 * H) + nb * 64 + tx * 4 + q], acc[i][q]);
}

// ---------------- k2: LSTM combine ----------------
__global__ void k_lstm_combine(float* __restrict__ dout,
                               const float* __restrict__ c0,
                               const float* __restrict__ b_ih,
                               const float* __restrict__ b_hh) {
    int b = blockIdx.x, j = threadIdx.x;
    const float* gr = g_gates + b * (4 * H);
    float ig = gr[j]        + b_ih[j]        + b_hh[j];
    float fg = gr[512 + j]  + b_ih[512 + j]  + b_hh[512 + j];
    float gg = gr[1024 + j] + b_ih[1024 + j] + b_hh[1024 + j];
    float og = gr[1536 + j] + b_ih[1536 + j] + b_hh[1536 + j];
    float c = sigmoidf_(fg) * c0[b * H + j] + sigmoidf_(ig) * tanhf(gg);
    float h = sigmoidf_(og) * tanhf(c);
    g_hnew[b * H + j] = h;
    g_dec_bf16[b * H + j] = __float2bfloat16(h);
    dout[OUT_H_OFF + (size_t)b * H + j] = h;
    dout[OUT_C_OFF + (size_t)b * H + j] = c;
}

// ---------------- k4: attention with fused phase-0 query GEMV ----------------
__global__ void k_attn(const float* __restrict__ enc, const float* __restrict__ cenc,
                       const float* __restrict__ attn_W, const float* __restrict__ attn_b,
                       const float* __restrict__ cattn_W, const float* __restrict__ cattn_b) {
    __shared__ float sh[H];          // h[b]
    __shared__ float sd[H];          // query vector d1/d2
    __shared__ float s_acc[16][H];
    __shared__ float s_wm[16], s_wl[16];
    int bb = blockIdx.x;
    bool is_ctx = bb >= B;
    int b = bb & (B - 1);
    const float* base = is_ctx ? cenc : enc;
    const float* Wq   = is_ctx ? cattn_W : attn_W;
    const float* bq   = is_ctx ? cattn_b : attn_b;
    int tid = threadIdx.x;
    int w = tid >> 5, lane = tid & 31;

    // phase 0: d[n] = bq[n] + attn-W row n . h[b]   (warp per output, coalesced)
    if (tid < H) sh[tid] = g_hnew[b * H + tid];
    __syncthreads();
    for (int n = w; n < H; n += 16) {
        const float* Wrow = Wq + (size_t)n * H;
        float acc = 0.f;
#pragma unroll
        for (int k = lane * 4; k < H; k += 128) {
            float4 wv = *(const float4*)(Wrow + k);
            acc += wv.x * sh[k] + wv.y * sh[k + 1] + wv.z * sh[k + 2] + wv.w * sh[k + 3];
        }
#pragma unroll
        for (int off = 16; off; off >>= 1) acc += __shfl_xor_sync(0xFFFFFFFFu, acc, off);
        if (lane == 0) sd[n] = acc + bq[n];
    }
    __syncthreads();
    float4 dv0 = ((const float4*)sd)[lane];
    float4 dv1 = ((const float4*)sd)[lane + 32];
    float4 dv2 = ((const float4*)sd)[lane + 64];
    float4 dv3 = ((const float4*)sd)[lane + 96];

    float m = -INFINITY, l = 0.f;
    float4 a0 = {0,0,0,0}, a1 = {0,0,0,0}, a2 = {0,0,0,0}, a3 = {0,0,0,0};

    int t = w;
    const float4* rp = (const float4*)(base + ((size_t)b * T + t) * H);
    float4 v0 = rp[lane], v1 = rp[lane + 32], v2 = rp[lane + 64], v3 = rp[lane + 96];

    for (int it = 0; it < 64; ++it) {
        float4 c0 = v0, c1 = v1, c2 = v2, c3 = v3;
        int tn = t + 16;
        if (it < 63) {
            const float4* rn = (const float4*)(base + ((size_t)b * T + tn) * H);
            v0 = rn[lane]; v1 = rn[lane + 32]; v2 = rn[lane + 64]; v3 = rn[lane + 96];
        }
        float p = c0.x*dv0.x + c0.y*dv0.y + c0.z*dv0.z + c0.w*dv0.w
                + c1.x*dv1.x + c1.y*dv1.y + c1.z*dv1.z + c1.w*dv1.w
                + c2.x*dv2.x + c2.y*dv2.y + c2.z*dv2.z + c2.w*dv2.w
                + c3.x*dv3.x + c3.y*dv3.y + c3.z*dv3.z + c3.w*dv3.w;
#pragma unroll
        for (int off = 16; off; off >>= 1) p += __shfl_xor_sync(0xFFFFFFFFu, p, off);
        if (is_ctx && lane == 0) g_scores[b * TCC + t] = p;
        float mn = fmaxf(m, p);
        float e  = __expf(p - mn);
        float sc = __expf(m - mn);
        l = l * sc + e;
        a0.x = a0.x*sc + e*c0.x; a0.y = a0.y*sc + e*c0.y; a0.z = a0.z*sc + e*c0.z; a0.w = a0.w*sc + e*c0.w;
        a1.x = a1.x*sc + e*c1.x; a1.y = a1.y*sc + e*c1.y; a1.z = a1.z*sc + e*c1.z; a1.w = a1.w*sc + e*c1.w;
        a2.x = a2.x*sc + e*c2.x; a2.y = a2.y*sc + e*c2.y; a2.z = a2.z*sc + e*c2.z; a2.w = a2.w*sc + e*c2.w;
        a3.x = a3.x*sc + e*c3.x; a3.y = a3.y*sc + e*c3.y; a3.z = a3.z*sc + e*c3.z; a3.w = a3.w*sc + e*c3.w;
        m = mn;
        t = tn;
    }
    if (lane == 0) { s_wm[w] = m; s_wl[w] = l; }
    __syncthreads();
    float M = -INFINITY;
#pragma unroll
    for (int i = 0; i < 16; i++) M = fmaxf(M, s_wm[i]);
    float L = 0.f;
#pragma unroll
    for (int i = 0; i < 16; i++) L += s_wl[i] * __expf(s_wm[i] - M);
    float f = __expf(m - M);
    float4* srow = (float4*)s_acc[w];
    float4 t0 = a0; t0.x*=f; t0.y*=f; t0.z*=f; t0.w*=f; srow[lane]      = t0;
    float4 t1 = a1; t1.x*=f; t1.y*=f; t1.z*=f; t1.w*=f; srow[lane + 32] = t1;
    float4 t2 = a2; t2.x*=f; t2.y*=f; t2.z*=f; t2.w*=f; srow[lane + 64] = t2;
    float4 t3 = a3; t3.x*=f; t3.y*=f; t3.z*=f; t3.w*=f; srow[lane + 96] = t3;
    __syncthreads();
    if (tid < H) {
        float s = 0.f;
#pragma unroll
        for (int ww = 0; ww < 16; ww++) s += s_acc[ww][tid];
        float* outp = is_ctx ? g_cctx : g_ctx;
        outp[b * H + tid] = s / L;
    }
    if (is_ctx && tid == 0) { g_m2[b] = M; g_l2[b] = L; }
}

// ---------------- k6: vocab GEMM, register double-buffered (R11 proven) ----------------
__device__ __forceinline__ void mma16816(float* c, const uint32_t* a, const uint32_t* bb) {
    asm volatile(
        "mma.sync.aligned.m16n8k16.row.col.f32.bf16.bf16.f32 "
        "{%0,%1,%2,%3},{%4,%5,%6,%7},{%8,%9},{%0,%1,%2,%3};\n"
        : "+f"(c[0]), "+f"(c[1]), "+f"(c[2]), "+f"(c[3])
        : "r"(a[0]), "r"(a[1]), "r"(a[2]), "r"(a[3]), "r"(bb[0]), "r"(bb[1]));
}

__global__ void k_logits(const float* __restrict__ out_W, const float* __restrict__ out_b,
                         float* __restrict__ dout) {
    if (blockIdx.x == 625) {   // zero OOV tail
        for (int i = threadIdx.x; i < B * OOV; i += 256) {
            int b = i / OOV, v = VT + i % OOV;
            dout[(size_t)b * VO + v] = 0.f;
        }
        return;
    }
    __shared__ __align__(16) __nv_bfloat16 As[128 * 40];
    __shared__ __align__(16) __nv_bfloat16 Bs[80 * 40];
    __shared__ float s_rsum[128];
    int tid = threadIdx.x;                 // 256
    int w = tid >> 5, lane = tid & 31;
    int gid = lane >> 2, tg = lane & 3;
    int wm = w & 3, wn = w >> 2;
    int nbase = blockIdx.x * 80;
    float acc[2][5][4];
#pragma unroll
    for (int mi = 0; mi < 2; mi++)
#pragma unroll
        for (int ni = 0; ni < 5; ni++)
#pragma unroll
            for (int q = 0; q < 4; q++) acc[mi][ni][q] = 0.f;
    for (int i = tid; i < 128; i += 256) s_rsum[i] = 0.f;

    int arow0 = tid >> 2,          aseg0 = tid & 3;
    int arow1 = (tid + 256) >> 2,  aseg1 = tid & 3;
    int bn0 = tid >> 3,            bk0 = tid & 7;
    int bn1 = (tid + 256) >> 3,    bk1 = tid & 7;
    int bn2 = (tid + 512) >> 3,    bk2 = tid & 7;

    uint4 ra0, ra1;
    float4 rb0, rb1, rb2;

    ra0 = *(const uint4*)(g_dec_bf16 + arow0 * H + aseg0 * 8);
    ra1 = *(const uint4*)(g_dec_bf16 + arow1 * H + aseg1 * 8);
    rb0 = *(const float4*)(out_W + (size_t)(nbase + bn0) * H + bk0 * 4);
    rb1 = *(const float4*)(out_W + (size_t)(nbase + bn1) * H + bk1 * 4);
    if (tid < 128) rb2 = *(const float4*)(out_W + (size_t)(nbase + bn2) * H + bk2 * 4);

    for (int kc = 0; kc < 16; kc++) {
        *(uint4*)(As + arow0 * 40 + aseg0 * 8) = ra0;
        *(uint4*)(As + arow1 * 40 + aseg1 * 8) = ra1;
        {
            __nv_bfloat162* p0 = (__nv_bfloat162*)(Bs + bn0 * 40 + bk0 * 4);
            p0[0] = __floats2bfloat162_rn(rb0.x, rb0.y);
            p0[1] = __floats2bfloat162_rn(rb0.z, rb0.w);
            __nv_bfloat162* p1 = (__nv_bfloat162*)(Bs + bn1 * 40 + bk1 * 4);
            p1[0] = __floats2bfloat162_rn(rb1.x, rb1.y);
            p1[1] = __floats2bfloat162_rn(rb1.z, rb1.w);
            if (tid < 128) {
                __nv_bfloat162* p2 = (__nv_bfloat162*)(Bs + bn2 * 40 + bk2 * 4);
                p2[0] = __floats2bfloat162_rn(rb2.x, rb2.y);
                p2[1] = __floats2bfloat162_rn(rb2.z, rb2.w);
            }
        }
        __syncthreads();
        if (kc < 15) {
            int kk = (kc + 1) * 32;
            ra0 = *(const uint4*)(g_dec_bf16 + arow0 * H + kk + aseg0 * 8);
            ra1 = *(const uint4*)(g_dec_bf16 + arow1 * H + kk + aseg1 * 8);
            rb0 = *(const float4*)(out_W + (size_t)(nbase + bn0) * H + kk + bk0 * 4);
            rb1 = *(const float4*)(out_W + (size_t)(nbase + bn1) * H + kk + bk1 * 4);
            if (tid < 128) rb2 = *(const float4*)(out_W + (size_t)(nbase + bn2) * H + kk + bk2 * 4);
        }
#pragma unroll
        for (int ks = 0; ks < 32; ks += 16) {
            uint32_t a[2][4], bfr[5][2];
#pragma unroll
            for (int mi = 0; mi < 2; mi++) {
                int rb = wm * 32 + mi * 16;
                a[mi][0] = *(const uint32_t*)(As + (rb + gid) * 40 + ks + tg * 2);
                a[mi][1] = *(const uint32_t*)(As + (rb + gid + 8) * 40 + ks + tg * 2);
                a[mi][2] = *(const uint32_t*)(As + (rb + gid) * 40 + ks + tg * 2 + 8);
                a[mi][3] = *(const uint32_t*)(As + (rb + gid + 8) * 40 + ks + tg * 2 + 8);
            }
#pragma unroll
            for (int ni = 0; ni < 5; ni++) {
                int cb = wn * 40 + ni * 8;
                bfr[ni][0] = *(const uint32_t*)(Bs + (cb + gid) * 40 + ks + tg * 2);
                bfr[ni][1] = *(const uint32_t*)(Bs + (cb + gid) * 40 + ks + tg * 2 + 8);
            }
#pragma unroll
            for (int mi = 0; mi < 2; mi++)
#pragma unroll
                for (int ni = 0; ni < 5; ni++) mma16816(acc[mi][ni], a[mi], bfr[ni]);
        }
        __syncthreads();
    }
#pragma unroll
    for (int mi = 0; mi < 2; mi++) {
        int row0 = wm * 32 + mi * 16 + gid;
        float rs0 = 0.f, rs1 = 0.f;
#pragma unroll
        for (int ni = 0; ni < 5; ni++) {
            int col = nbase + wn * 40 + ni * 8 + tg * 2;
            float b0 = out_b[col], b1 = out_b[col + 1];
            float e0 = __expf(acc[mi][ni][0] + b0);
            float e1 = __expf(acc[mi][ni][1] + b1);
            float e2 = __expf(acc[mi][ni][2] + b0);
            float e3 = __expf(acc[mi][ni][3] + b1);
            dout[(size_t)row0 * VO + col]           = e0;
            dout[(size_t)row0 * VO + col + 1]       = e1;
            dout[(size_t)(row0 + 8) * VO + col]     = e2;
            dout[(size_t)(row0 + 8) * VO + col + 1] = e3;
            rs0 += e0 + e1;
            rs1 += e2 + e3;
        }
        atomicAdd(&s_rsum[row0], rs0);
        atomicAdd(&s_rsum[row0 + 8], rs1);
    }
    __syncthreads();
    for (int i = tid; i < 128; i += 256) atomicAdd(&g_rsum[i], s_rsum[i]);
}

// ---------------- k7: fused p_gen + scatter + scale + log ----------------
__global__ void __launch_bounds__(512)
k_pgen_scatter_log(float* __restrict__ dout, const int* __restrict__ ci,
                   const float* __restrict__ gen_W, const float* __restrict__ gen_b,
                   const float* __restrict__ sig_b) {
    int b = blockIdx.x, tid = threadIdx.x;  // 128 x 512
    int w = tid >> 5, lane = tid & 31;
    __shared__ float sp[16]; __shared__ int scn[16];
    __shared__ float s_coef, s_A;

    float part = 0.f;
    for (int i = tid; i < 3 * H + E; i += 512) {
        float v;
        if (i < 512)        v = g_ctx[b * H + i];
        else if (i < 1024)  v = g_cctx[b * H + i - 512];
        else if (i < 1536)  v = g_hnew[b * H + i - 1024];
        else                v = g_x[b * E + i - 1536];
        part += v * gen_W[i];
    }
    int cnt = 0;
    for (int tt = tid; tt < TCC; tt += 512) cnt += (ci[b * TCC + tt] > 0);
#pragma unroll
    for (int off = 16; off; off >>= 1) {
        part += __shfl_xor_sync(0xFFFFFFFFu, part, off);
        cnt  += __shfl_xor_sync(0xFFFFFFFFu, cnt, off);
    }
    if (lane == 0) { sp[w] = part; scn[w] = cnt; }
    __syncthreads();
    if (tid == 0) {
        float s = 0.f; int c = 0;
#pragma unroll
        for (int i = 0; i < 16; i++) { s += sp[i]; c += scn[i]; }
        float pg = sigmoidf_(s + gen_b[0] + sig_b[0]);
        if (c == 0) pg = 1.f;
        float A = pg / g_rsum[b];
        s_A = A;
        s_coef = (1.f - pg) / g_l2[b] / A;
    }
    __syncthreads();

    float coef = s_coef;
    float m2 = g_m2[b];
    for (int t = tid; t < TCC; t += 512) {
        int id = ci[b * TCC + t];
        float val = coef * __expf(g_scores[b * TCC + t] - m2);
        atomicAdd(dout + (size_t)b * VO + id, val);
    }
    __threadfence();
    __syncthreads();

    float A = s_A;
    float* row = dout + (size_t)b * VO;
    for (int v = tid; v < VO; v += 512) {
        row[v] = __logf(fmaxf(A * row[v], 1e-10f));
    }
}

// ---------------- launch (fork/join: logits ∥ attn) ----------------
extern "C" void kernel_launch(void* const* d_in, const int* in_sizes, int n_in,
                              void* d_out, int out_size) {
    const int*   input_ids = (const int*)  d_in[0];
    const float* h0        = (const float*)d_in[1];
    const float* c0        = (const float*)d_in[2];
    const float* enc       = (const float*)d_in[3];
    const float* cenc      = (const float*)d_in[4];
    const int*   ci        = (const int*)  d_in[5];
    const float* emb       = (const float*)d_in[6];
    const float* W_ih      = (const float*)d_in[7];
    const float* W_hh      = (const float*)d_in[8];
    const float* b_ih      = (const float*)d_in[9];
    const float* b_hh      = (const float*)d_in[10];
    const float* attn_W    = (const float*)d_in[11];
    const float* attn_b    = (const float*)d_in[12];
    const float* cattn_W   = (const float*)d_in[13];
    const float* cattn_b   = (const float*)d_in[14];
    const float* gen_W     = (const float*)d_in[15];
    const float* gen_b     = (const float*)d_in[16];
    const float* sig_b     = (const float*)d_in[17];
    const float* out_W     = (const float*)d_in[18];
    const float* out_b     = (const float*)d_in[19];
    float* dout = (float*)d_out;

    k_embed<<<B, 256>>>(input_ids, emb);
    k_lstm_gemm<<<dim3(32, 16), 256>>>(h0, W_ih, W_hh);
    k_lstm_combine<<<B, 512>>>(dout, c0, b_ih, b_hh);

    cudaStream_t s2;
    cudaEvent_t evFork, evJoin;
    cudaStreamCreateWithFlags(&s2, cudaStreamNonBlocking);
    cudaEventCreateWithFlags(&evFork, cudaEventDisableTiming);
    cudaEventCreateWithFlags(&evJoin, cudaEventDisableTiming);

    cudaEventRecord(evFork, 0);
    cudaStreamWaitEvent(s2, evFork, 0);
    k_logits<<<626, 256, 0, s2>>>(out_W, out_b, dout);
    cudaEventRecord(evJoin, s2);

    k_attn<<<2 * B, 512>>>(enc, cenc, attn_W, attn_b, cattn_W, cattn_b);

    cudaStreamWaitEvent(0, evJoin, 0);

    k_pgen_scatter_log<<<B, 512>>>(dout, ci, gen_W, gen_b, sig_b);
}

// round 17
// speedup vs baseline: 1.1624x; 1.1624x over previous
#include <cuda_runtime.h>
#include <cuda_bf16.h>
#include <cuda_pipeline.h>
#include <math.h>
#include <stdint.h>

#define B   128
#define T   1024
#define TCC 1024
#define H   512
#define E   256
#define VT  50000
#define OOV 50
#define VO  (VT + OOV)

#define OUT_H_OFF ((size_t)B * VO)
#define OUT_C_OFF (OUT_H_OFF + (size_t)B * H)

// attention pipeline depth (power of 2)
#define AD 4
// dynamic smem layout: sd(2048) | s_wm(64) | s_wl(64) | s_acc(32768) | ring(16*AD*2048)
#define OFF_WM   2048
#define OFF_WL   (2048 + 64)
#define OFF_ACC  (2048 + 128)
#define OFF_RING (OFF_ACC + 32768)
#define ATTN_SMEM (OFF_RING + 16 * AD * 2048)

// ---------------- scratch ----------------
__device__ float g_x[B * E];
__device__ float g_gates[B * 4 * H];
__device__ float g_hnew[B * H];
__device__ float g_d12[B * 2 * H];
__device__ __align__(16) __nv_bfloat16 g_dec_bf16[B * H];
__device__ float g_ctx[B * H];
__device__ float g_cctx[B * H];
__device__ float g_scores[B * TCC];
__device__ float g_m2[B], g_l2[B];
__device__ float g_rsum[B];

__device__ __forceinline__ float sigmoidf_(float x) { return 1.f / (1.f + expf(-x)); }

// ---------------- k0: embed (+ zero gates & rsum) ----------------
__global__ void k_embed(const int* __restrict__ ids, const float* __restrict__ emb) {
    int b = blockIdx.x, e = threadIdx.x;
    float s = 0.f;
#pragma unroll
    for (int l = 0; l < 4; l++) {
        int id = ids[b * 4 + l];
        s += emb[(size_t)id * E + e];
    }
    g_x[b * E + e] = tanhf(s * 0.25f);
    int idx = b * 256 + e;
    for (int i = idx; i < B * 4 * H; i += B * 256) g_gates[i] = 0.f;
    if (idx < B) g_rsum[idx] = 0.f;
}

// ---------------- k1: LSTM gates GEMM, split-K x16 ----------------
__global__ void k_lstm_gemm(const float* __restrict__ h0,
                            const float* __restrict__ W_ih,
                            const float* __restrict__ W_hh) {
    __shared__ float As[128][17];
    __shared__ float Ws[64][17];
    int tid = threadIdx.x;
    int tx = tid & 15, ty = tid >> 4;
    int nb = blockIdx.x;
    int ksp = blockIdx.y;        // K range [ksp*48, +48)
    float acc[8][4];
#pragma unroll
    for (int i = 0; i < 8; i++)
#pragma unroll
        for (int q = 0; q < 4; q++) acc[i][q] = 0.f;

#pragma unroll
    for (int kk = 0; kk < 48; kk += 16) {
        int kg0 = ksp * 48 + kk;
        for (int i = tid; i < 128 * 16; i += 256) {
            int m = i >> 4, kc = i & 15, kg = kg0 + kc;
            As[m][kc] = (kg < 256) ? g_x[m * E + kg] : h0[m * H + (kg - 256)];
        }
        for (int i = tid; i < 64 * 16; i += 256) {
            int n = i >> 4, kc = i & 15, kg = kg0 + kc;
            int ng = nb * 64 + n;
            Ws[n][kc] = (kg < 256) ? W_ih[(size_t)ng * 256 + kg]
                                   : W_hh[(size_t)ng * 512 + (kg - 256)];
        }
        __syncthreads();
#pragma unroll
        for (int k = 0; k < 16; k++) {
            float a[8], wv[4];
#pragma unroll
            for (int i = 0; i < 8; i++) a[i] = As[ty + 16 * i][k];
#pragma unroll
            for (int q = 0; q < 4; q++) wv[q] = Ws[tx * 4 + q][k];
#pragma unroll
            for (int i = 0; i < 8; i++)
#pragma unroll
                for (int q = 0; q < 4; q++) acc[i][q] += a[i] * wv[q];
        }
        __syncthreads();
    }
#pragma unroll
    for (int i = 0; i < 8; i++)
#pragma unroll
        for (int q = 0; q < 4; q++)
            atomicAdd(&g_gates[(ty + 16 * i) * (4 * H) + nb * 64 + tx * 4 + q], acc[i][q]);
}

// ---------------- k2: LSTM combine (+ d12 bias init) ----------------
__global__ void k_lstm_combine(float* __restrict__ dout,
                               const float* __restrict__ c0,
                               const float* __restrict__ b_ih,
                               const float* __restrict__ b_hh,
                               const float* __restrict__ attn_b,
                               const float* __restrict__ cattn_b) {
    int b = blockIdx.x, j = threadIdx.x;
    const float* gr = g_gates + b * (4 * H);
    float ig = gr[j]        + b_ih[j]        + b_hh[j];
    float fg = gr[512 + j]  + b_ih[512 + j]  + b_hh[512 + j];
    float gg = gr[1024 + j] + b_ih[1024 + j] + b_hh[1024 + j];
    float og = gr[1536 + j] + b_ih[1536 + j] + b_hh[1536 + j];
    float c = sigmoidf_(fg) * c0[b * H + j] + sigmoidf_(ig) * tanhf(gg);
    float h = sigmoidf_(og) * tanhf(c);
    g_hnew[b * H + j] = h;
    g_dec_bf16[b * H + j] = __float2bfloat16(h);
    dout[OUT_H_OFF + (size_t)b * H + j] = h;
    dout[OUT_C_OFF + (size_t)b * H + j] = c;
    g_d12[b * (2 * H) + j]     = attn_b[j];
    g_d12[b * (2 * H) + H + j] = cattn_b[j];
}

// ---------------- k3: d1/d2 += dec @ W^T, split-K x16 ----------------
__global__ void k_d12(const float* __restrict__ attn_W,
                      const float* __restrict__ cattn_W) {
    __shared__ float As[128][17];
    __shared__ float Ws[64][17];
    int tid = threadIdx.x;
    int tx = tid & 15, ty = tid >> 4;
    int nb = blockIdx.x;
    int ksp = blockIdx.y;
    float acc[8][4];
#pragma unroll
    for (int i = 0; i < 8; i++)
#pragma unroll
        for (int q = 0; q < 4; q++) acc[i][q] = 0.f;

#pragma unroll
    for (int kk = 0; kk < 32; kk += 16) {
        int kg0 = ksp * 32 + kk;
        for (int i = tid; i < 128 * 16; i += 256) {
            int m = i >> 4, kc = i & 15;
            As[m][kc] = g_hnew[(size_t)m * H + kg0 + kc];
        }
        for (int i = tid; i < 64 * 16; i += 256) {
            int n = i >> 4, kc = i & 15;
            int ng = nb * 64 + n;
            Ws[n][kc] = (ng < 512) ? attn_W[(size_t)ng * H + kg0 + kc]
                                   : cattn_W[(size_t)(ng - 512) * H + kg0 + kc];
        }
        __syncthreads();
#pragma unroll
        for (int k = 0; k < 16; k++) {
            float a[8], wv[4];
#pragma unroll
            for (int i = 0; i < 8; i++) a[i] = As[ty + 16 * i][k];
#pragma unroll
            for (int q = 0; q < 4; q++) wv[q] = Ws[tx * 4 + q][k];
#pragma unroll
            for (int i = 0; i < 8; i++)
#pragma unroll
                for (int q = 0; q < 4; q++) acc[i][q] += a[i] * wv[q];
        }
        __syncthreads();
    }
#pragma unroll
    for (int i = 0; i < 8; i++)
#pragma unroll
        for (int q = 0; q < 4; q++)
            atomicAdd(&g_d12[(ty + 16 * i) * (2 * H) + nb * 64 + tx * 4 + q], acc[i][q]);
}

// ---------------- k4: attention with cp.async smem ring (depth AD) ----------------
__global__ void k_attn(const float* __restrict__ enc, const float* __restrict__ cenc) {
    extern __shared__ __align__(16) char sm[];
    float* sd   = (float*)sm;
    float* s_wm = (float*)(sm + OFF_WM);
    float* s_wl = (float*)(sm + OFF_WL);
    float (*s_acc)[H] = (float(*)[H])(sm + OFF_ACC);
    int bb = blockIdx.x;
    bool is_ctx = bb >= B;
    int b = bb & (B - 1);
    const float* base = is_ctx ? cenc : enc;
    const float* dvecp = g_d12 + b * (2 * H) + (is_ctx ? 512 : 0);
    int tid = threadIdx.x;           // 512
    int w = tid >> 5, lane = tid & 31;
    float* myring = (float*)(sm + OFF_RING) + w * (AD * 512);
    const float* gsrc = base + (size_t)b * T * H;

    if (tid < H) sd[tid] = dvecp[tid];
    __syncthreads();
    float4 dv0 = ((const float4*)sd)[lane];
    float4 dv1 = ((const float4*)sd)[lane + 32];
    float4 dv2 = ((const float4*)sd)[lane + 64];
    float4 dv3 = ((const float4*)sd)[lane + 96];

    float m = -INFINITY, l = 0.f;
    float4 a0 = {0,0,0,0}, a1 = {0,0,0,0}, a2 = {0,0,0,0}, a3 = {0,0,0,0};

    // prologue: stage rows w, w+16, w+32 (AD-1 rows)
#pragma unroll
    for (int d = 0; d < AD - 1; d++) {
        const float4* src = (const float4*)(gsrc + (size_t)(w + d * 16) * H);
        float4* dst = (float4*)(myring + d * 512);
        __pipeline_memcpy_async(&dst[lane],      &src[lane],      16);
        __pipeline_memcpy_async(&dst[lane + 32], &src[lane + 32], 16);
        __pipeline_memcpy_async(&dst[lane + 64], &src[lane + 64], 16);
        __pipeline_memcpy_async(&dst[lane + 96], &src[lane + 96], 16);
        __pipeline_commit();
    }

    for (int it = 0; it < 64; ++it) {
        int nr = it + AD - 1;
        if (nr < 64) {
            const float4* src = (const float4*)(gsrc + (size_t)(w + nr * 16) * H);
            float4* dst = (float4*)(myring + (nr & (AD - 1)) * 512);
            __pipeline_memcpy_async(&dst[lane],      &src[lane],      16);
            __pipeline_memcpy_async(&dst[lane + 32], &src[lane + 32], 16);
            __pipeline_memcpy_async(&dst[lane + 64], &src[lane + 64], 16);
            __pipeline_memcpy_async(&dst[lane + 96], &src[lane + 96], 16);
        }
        __pipeline_commit();
        __pipeline_wait_prior(AD - 1);

        const float4* rowp = (const float4*)(myring + (it & (AD - 1)) * 512);
        float4 c0 = rowp[lane], c1 = rowp[lane + 32], c2 = rowp[lane + 64], c3 = rowp[lane + 96];
        float p = c0.x*dv0.x + c0.y*dv0.y + c0.z*dv0.z + c0.w*dv0.w
                + c1.x*dv1.x + c1.y*dv1.y + c1.z*dv1.z + c1.w*dv1.w
                + c2.x*dv2.x + c2.y*dv2.y + c2.z*dv2.z + c2.w*dv2.w
                + c3.x*dv3.x + c3.y*dv3.y + c3.z*dv3.z + c3.w*dv3.w;
#pragma unroll
        for (int off = 16; off; off >>= 1) p += __shfl_xor_sync(0xFFFFFFFFu, p, off);
        if (is_ctx && lane == 0) g_scores[b * TCC + w + it * 16] = p;
        float mn = fmaxf(m, p);
        float e  = __expf(p - mn);
        float sc = __expf(m - mn);
        l = l * sc + e;
        a0.x = a0.x*sc + e*c0.x; a0.y = a0.y*sc + e*c0.y; a0.z = a0.z*sc + e*c0.z; a0.w = a0.w*sc + e*c0.w;
        a1.x = a1.x*sc + e*c1.x; a1.y = a1.y*sc + e*c1.y; a1.z = a1.z*sc + e*c1.z; a1.w = a1.w*sc + e*c1.w;
        a2.x = a2.x*sc + e*c2.x; a2.y = a2.y*sc + e*c2.y; a2.z = a2.z*sc + e*c2.z; a2.w = a2.w*sc + e*c2.w;
        a3.x = a3.x*sc + e*c3.x; a3.y = a3.y*sc + e*c3.y; a3.z = a3.z*sc + e*c3.z; a3.w = a3.w*sc + e*c3.w;
        m = mn;
    }
    if (lane == 0) { s_wm[w] = m; s_wl[w] = l; }
    __syncthreads();
    float M = -INFINITY;
#pragma unroll
    for (int i = 0; i < 16; i++) M = fmaxf(M, s_wm[i]);
    float L = 0.f;
#pragma unroll
    for (int i = 0; i < 16; i++) L += s_wl[i] * __expf(s_wm[i] - M);
    float f = __expf(m - M);
    float4* srow = (float4*)s_acc[w];
    float4 t0 = a0; t0.x*=f; t0.y*=f; t0.z*=f; t0.w*=f; srow[lane]      = t0;
    float4 t1 = a1; t1.x*=f; t1.y*=f; t1.z*=f; t1.w*=f; srow[lane + 32] = t1;
    float4 t2 = a2; t2.x*=f; t2.y*=f; t2.z*=f; t2.w*=f; srow[lane + 64] = t2;
    float4 t3 = a3; t3.x*=f; t3.y*=f; t3.z*=f; t3.w*=f; srow[lane + 96] = t3;
    __syncthreads();
    if (tid < H) {
        float s = 0.f;
#pragma unroll
        for (int ww = 0; ww < 16; ww++) s += s_acc[ww][tid];
        float* outp = is_ctx ? g_cctx : g_ctx;
        outp[b * H + tid] = s / L;
    }
    if (is_ctx && tid == 0) { g_m2[b] = M; g_l2[b] = L; }
}

// ---------------- k6: vocab GEMM, register double-buffered (R11 proven) ----------------
__device__ __forceinline__ void mma16816(float* c, const uint32_t* a, const uint32_t* bb) {
    asm volatile(
        "mma.sync.aligned.m16n8k16.row.col.f32.bf16.bf16.f32 "
        "{%0,%1,%2,%3},{%4,%5,%6,%7},{%8,%9},{%0,%1,%2,%3};\n"
        : "+f"(c[0]), "+f"(c[1]), "+f"(c[2]), "+f"(c[3])
        : "r"(a[0]), "r"(a[1]), "r"(a[2]), "r"(a[3]), "r"(bb[0]), "r"(bb[1]));
}

__global__ void k_logits(const float* __restrict__ out_W, const float* __restrict__ out_b,
                         float* __restrict__ dout) {
    if (blockIdx.x == 625) {   // zero OOV tail
        for (int i = threadIdx.x; i < B * OOV; i += 256) {
            int b = i / OOV, v = VT + i % OOV;
            dout[(size_t)b * VO + v] = 0.f;
        }
        return;
    }
    __shared__ __align__(16) __nv_bfloat16 As[128 * 40];
    __shared__ __align__(16) __nv_bfloat16 Bs[80 * 40];
    __shared__ float s_rsum[128];
    int tid = threadIdx.x;                 // 256
    int w = tid >> 5, lane = tid & 31;
    int gid = lane >> 2, tg = lane & 3;
    int wm = w & 3, wn = w >> 2;
    int nbase = blockIdx.x * 80;
    float acc[2][5][4];
#pragma unroll
    for (int mi = 0; mi < 2; mi++)
#pragma unroll
        for (int ni = 0; ni < 5; ni++)
#pragma unroll
            for (int q = 0; q < 4; q++) acc[mi][ni][q] = 0.f;
    for (int i = tid; i < 128; i += 256) s_rsum[i] = 0.f;

    int arow0 = tid >> 2,          aseg0 = tid & 3;
    int arow1 = (tid + 256) >> 2,  aseg1 = tid & 3;
    int bn0 = tid >> 3,            bk0 = tid & 7;
    int bn1 = (tid + 256) >> 3,    bk1 = tid & 7;
    int bn2 = (tid + 512) >> 3,    bk2 = tid & 7;

    uint4 ra0, ra1;
    float4 rb0, rb1, rb2;

    ra0 = *(const uint4*)(g_dec_bf16 + arow0 * H + aseg0 * 8);
    ra1 = *(const uint4*)(g_dec_bf16 + arow1 * H + aseg1 * 8);
    rb0 = *(const float4*)(out_W + (size_t)(nbase + bn0) * H + bk0 * 4);
    rb1 = *(const float4*)(out_W + (size_t)(nbase + bn1) * H + bk1 * 4);
    if (tid < 128) rb2 = *(const float4*)(out_W + (size_t)(nbase + bn2) * H + bk2 * 4);

    for (int kc = 0; kc < 16; kc++) {
        *(uint4*)(As + arow0 * 40 + aseg0 * 8) = ra0;
        *(uint4*)(As + arow1 * 40 + aseg1 * 8) = ra1;
        {
            __nv_bfloat162* p0 = (__nv_bfloat162*)(Bs + bn0 * 40 + bk0 * 4);
            p0[0] = __floats2bfloat162_rn(rb0.x, rb0.y);
            p0[1] = __floats2bfloat162_rn(rb0.z, rb0.w);
            __nv_bfloat162* p1 = (__nv_bfloat162*)(Bs + bn1 * 40 + bk1 * 4);
            p1[0] = __floats2bfloat162_rn(rb1.x, rb1.y);
            p1[1] = __floats2bfloat162_rn(rb1.z, rb1.w);
            if (tid < 128) {
                __nv_bfloat162* p2 = (__nv_bfloat162*)(Bs + bn2 * 40 + bk2 * 4);
                p2[0] = __floats2bfloat162_rn(rb2.x, rb2.y);
                p2[1] = __floats2bfloat162_rn(rb2.z, rb2.w);
            }
        }
        __syncthreads();
        if (kc < 15) {
            int kk = (kc + 1) * 32;
            ra0 = *(const uint4*)(g_dec_bf16 + arow0 * H + kk + aseg0 * 8);
            ra1 = *(const uint4*)(g_dec_bf16 + arow1 * H + kk + aseg1 * 8);
            rb0 = *(const float4*)(out_W + (size_t)(nbase + bn0) * H + kk + bk0 * 4);
            rb1 = *(const float4*)(out_W + (size_t)(nbase + bn1) * H + kk + bk1 * 4);
            if (tid < 128) rb2 = *(const float4*)(out_W + (size_t)(nbase + bn2) * H + kk + bk2 * 4);
        }
#pragma unroll
        for (int ks = 0; ks < 32; ks += 16) {
            uint32_t a[2][4], bfr[5][2];
#pragma unroll
            for (int mi = 0; mi < 2; mi++) {
                int rb = wm * 32 + mi * 16;
                a[mi][0] = *(const uint32_t*)(As + (rb + gid) * 40 + ks + tg * 2);
                a[mi][1] = *(const uint32_t*)(As + (rb + gid + 8) * 40 + ks + tg * 2);
                a[mi][2] = *(const uint32_t*)(As + (rb + gid) * 40 + ks + tg * 2 + 8);
                a[mi][3] = *(const uint32_t*)(As + (rb + gid + 8) * 40 + ks + tg * 2 + 8);
            }
#pragma unroll
            for (int ni = 0; ni < 5; ni++) {
                int cb = wn * 40 + ni * 8;
                bfr[ni][0] = *(const uint32_t*)(Bs + (cb + gid) * 40 + ks + tg * 2);
                bfr[ni][1] = *(const uint32_t*)(Bs + (cb + gid) * 40 + ks + tg * 2 + 8);
            }
#pragma unroll
            for (int mi = 0; mi < 2; mi++)
#pragma unroll
                for (int ni = 0; ni < 5; ni++) mma16816(acc[mi][ni], a[mi], bfr[ni]);
        }
        __syncthreads();
    }
#pragma unroll
    for (int mi = 0; mi < 2; mi++) {
        int row0 = wm * 32 + mi * 16 + gid;
        float rs0 = 0.f, rs1 = 0.f;
#pragma unroll
        for (int ni = 0; ni < 5; ni++) {
            int col = nbase + wn * 40 + ni * 8 + tg * 2;
            float b0 = out_b[col], b1 = out_b[col + 1];
            float e0 = __expf(acc[mi][ni][0] + b0);
            float e1 = __expf(acc[mi][ni][1] + b1);
            float e2 = __expf(acc[mi][ni][2] + b0);
            float e3 = __expf(acc[mi][ni][3] + b1);
            dout[(size_t)row0 * VO + col]           = e0;
            dout[(size_t)row0 * VO + col + 1]       = e1;
            dout[(size_t)(row0 + 8) * VO + col]     = e2;
            dout[(size_t)(row0 + 8) * VO + col + 1] = e3;
            rs0 += e0 + e1;
            rs1 += e2 + e3;
        }
        atomicAdd(&s_rsum[row0], rs0);
        atomicAdd(&s_rsum[row0 + 8], rs1);
    }
    __syncthreads();
    for (int i = tid; i < 128; i += 256) atomicAdd(&g_rsum[i], s_rsum[i]);
}

// ---------------- k7: fused p_gen + scatter + scale + log ----------------
__global__ void __launch_bounds__(512)
k_pgen_scatter_log(float* __restrict__ dout, const int* __restrict__ ci,
                   const float* __restrict__ gen_W, const float* __restrict__ gen_b,
                   const float* __restrict__ sig_b) {
    int b = blockIdx.x, tid = threadIdx.x;  // 128 x 512
    int w = tid >> 5, lane = tid & 31;
    __shared__ float sp[16]; __shared__ int scn[16];
    __shared__ float s_coef, s_A;

    float part = 0.f;
    for (int i = tid; i < 3 * H + E; i += 512) {
        float v;
        if (i < 512)        v = g_ctx[b * H + i];
        else if (i < 1024)  v = g_cctx[b * H + i - 512];
        else if (i < 1536)  v = g_hnew[b * H + i - 1024];
        else                v = g_x[b * E + i - 1536];
        part += v * gen_W[i];
    }
    int cnt = 0;
    for (int tt = tid; tt < TCC; tt += 512) cnt += (ci[b * TCC + tt] > 0);
#pragma unroll
    for (int off = 16; off; off >>= 1) {
        part += __shfl_xor_sync(0xFFFFFFFFu, part, off);
        cnt  += __shfl_xor_sync(0xFFFFFFFFu, cnt, off);
    }
    if (lane == 0) { sp[w] = part; scn[w] = cnt; }
    __syncthreads();
    if (tid == 0) {
        float s = 0.f; int c = 0;
#pragma unroll
        for (int i = 0; i < 16; i++) { s += sp[i]; c += scn[i]; }
        float pg = sigmoidf_(s + gen_b[0] + sig_b[0]);
        if (c == 0) pg = 1.f;
        float A = pg / g_rsum[b];
        s_A = A;
        s_coef = (1.f - pg) / g_l2[b] / A;
    }
    __syncthreads();

    float coef = s_coef;
    float m2 = g_m2[b];
    for (int t = tid; t < TCC; t += 512) {
        int id = ci[b * TCC + t];
        float val = coef * __expf(g_scores[b * TCC + t] - m2);
        atomicAdd(dout + (size_t)b * VO + id, val);
    }
    __threadfence();
    __syncthreads();

    float A = s_A;
    float* row = dout + (size_t)b * VO;
    for (int v = tid; v < VO; v += 512) {
        row[v] = __logf(fmaxf(A * row[v], 1e-10f));
    }
}

// ---------------- launch (fork/join: logits ∥ d12+attn) ----------------
extern "C" void kernel_launch(void* const* d_in, const int* in_sizes, int n_in,
                              void* d_out, int out_size) {
    const int*   input_ids = (const int*)  d_in[0];
    const float* h0        = (const float*)d_in[1];
    const float* c0        = (const float*)d_in[2];
    const float* enc       = (const float*)d_in[3];
    const float* cenc      = (const float*)d_in[4];
    const int*   ci        = (const int*)  d_in[5];
    const float* emb       = (const float*)d_in[6];
    const float* W_ih      = (const float*)d_in[7];
    const float* W_hh      = (const float*)d_in[8];
    const float* b_ih      = (const float*)d_in[9];
    const float* b_hh      = (const float*)d_in[10];
    const float* attn_W    = (const float*)d_in[11];
    const float* attn_b    = (const float*)d_in[12];
    const float* cattn_W   = (const float*)d_in[13];
    const float* cattn_b   = (const float*)d_in[14];
    const float* gen_W     = (const float*)d_in[15];
    const float* gen_b     = (const float*)d_in[16];
    const float* sig_b     = (const float*)d_in[17];
    const float* out_W     = (const float*)d_in[18];
    const float* out_b     = (const float*)d_in[19];
    float* dout = (float*)d_out;

    cudaFuncSetAttribute(k_attn, cudaFuncAttributeMaxDynamicSharedMemorySize, ATTN_SMEM);

    k_embed<<<B, 256>>>(input_ids, emb);
    k_lstm_gemm<<<dim3(32, 16), 256>>>(h0, W_ih, W_hh);
    k_lstm_combine<<<B, 512>>>(dout, c0, b_ih, b_hh, attn_b, cattn_b);

    cudaStream_t s2;
    cudaEvent_t evFork, evJoin;
    cudaStreamCreateWithFlags(&s2, cudaStreamNonBlocking);
    cudaEventCreateWithFlags(&evFork, cudaEventDisableTiming);
    cudaEventCreateWithFlags(&evJoin, cudaEventDisableTiming);

    cudaEventRecord(evFork, 0);
    cudaStreamWaitEvent(s2, evFork, 0);
    k_logits<<<626, 256, 0, s2>>>(out_W, out_b, dout);
    cudaEventRecord(evJoin, s2);

    k_d12<<<dim3(16, 16), 256>>>(attn_W, cattn_W);
    k_attn<<<2 * B, 512, ATTN_SMEM>>>(enc, cenc);

    cudaStreamWaitEvent(0, evJoin, 0);

    k_pgen_scatter_log<<<B, 512>>>(dout, ci, gen_W, gen_b, sig_b);
}